// round 4
// baseline (speedup 1.0000x reference)
#include <cuda_runtime.h>
#include <math.h>

// InputLayer: out[b,n,d] = LN_d( (x[b,n]*W[d] + bias[d]) * sqrt(1024) ) * gamma[d] + beta[d]
// Analytic LayerNorm (h affine in a=x[b,n]) -> closed-form mean/var from W/b stats.
// Single kernel, exactly ONE wave: grid = 148 SMs * 8 CTAs, rows split evenly.

#define SIZE 1024
#define QUADS (SIZE / 4)          // 256 threads per block
#define MAXR 64                   // max rows per block (smem bound)
#define LN_EPS 1e-5f
#define NSM 148
#define CTAS_PER_SM 8

__global__ __launch_bounds__(QUADS, CTAS_PER_SM)
void il_fused_kernel(const float* __restrict__ x,
                     const float* __restrict__ W,
                     const float* __restrict__ B,
                     const float* __restrict__ G,
                     const float* __restrict__ Be,
                     float* __restrict__ out,
                     int nrows) {
    const float SCALE = 32.0f;                 // sqrt(1024)
    const float S2 = SCALE * SCALE;

    int q = threadIdx.x;                       // 0..255
    int d0 = q * 4;

    // Even row partition: block i gets per (+1 if i < rem) contiguous rows.
    int nb  = gridDim.x;
    int per = nrows / nb;
    int rem = nrows - per * nb;
    int row0 = blockIdx.x * per + (blockIdx.x < rem ? blockIdx.x : rem);
    int cnt  = per + (blockIdx.x < rem ? 1 : 0);

    __shared__ float xa[MAXR];
    __shared__ float red[5][8];                // 5 stats x 8 warps

    if (q < cnt) xa[q] = x[row0 + q];

    float4 w4  = *(const float4*)(W  + d0);
    float4 b4  = *(const float4*)(B  + d0);
    float4 g4  = *(const float4*)(G  + d0);
    float4 be4 = *(const float4*)(Be + d0);

    // ---- per-block stats reduction over the 1024 (W,b) columns ----
    float s0 = w4.x + w4.y + w4.z + w4.w;
    float s1 = b4.x + b4.y + b4.z + b4.w;
    float s2 = w4.x*w4.x + w4.y*w4.y + w4.z*w4.z + w4.w*w4.w;
    float s3 = b4.x*b4.x + b4.y*b4.y + b4.z*b4.z + b4.w*b4.w;
    float s4 = w4.x*b4.x + w4.y*b4.y + w4.z*b4.z + w4.w*b4.w;

    int lane = q & 31, warp = q >> 5;
    #pragma unroll
    for (int o = 16; o > 0; o >>= 1) {
        s0 += __shfl_down_sync(0xffffffffu, s0, o);
        s1 += __shfl_down_sync(0xffffffffu, s1, o);
        s2 += __shfl_down_sync(0xffffffffu, s2, o);
        s3 += __shfl_down_sync(0xffffffffu, s3, o);
        s4 += __shfl_down_sync(0xffffffffu, s4, o);
    }
    if (lane == 0) {
        red[0][warp] = s0; red[1][warp] = s1; red[2][warp] = s2;
        red[3][warp] = s3; red[4][warp] = s4;
    }
    __syncthreads();

    float t0 = 0.f, t1 = 0.f, t2 = 0.f, t3 = 0.f, t4 = 0.f;
    #pragma unroll
    for (int i = 0; i < 8; i++) {
        t0 += red[0][i]; t1 += red[1][i]; t2 += red[2][i];
        t3 += red[3][i]; t4 += red[4][i];
    }
    const float inv = 1.0f / (float)SIZE;
    float mw = t0 * inv, mb = t1 * inv;
    float vw = fmaf(-mw, mw, t2 * inv);        // Var(W)
    float vb = fmaf(-mb, mb, t3 * inv);        // Var(B)
    float cv = fmaf(-mw, mb, t4 * inv);        // Cov(W,B)

    // P = (W - meanW) * gamma ;  Q = (B - meanB) * gamma   (w4/b4/g4 die here)
    float4 P, Q;
    P.x = (w4.x - mw) * g4.x;  Q.x = (b4.x - mb) * g4.x;
    P.y = (w4.y - mw) * g4.y;  Q.y = (b4.y - mb) * g4.y;
    P.z = (w4.z - mw) * g4.z;  Q.z = (b4.z - mb) * g4.z;
    P.w = (w4.w - mw) * g4.w;  Q.w = (b4.w - mb) * g4.w;

    float4* obase = (float4*)(out + (size_t)row0 * SIZE + d0);

    #pragma unroll 4
    for (int r = 0; r < cnt; r++) {
        float a = xa[r];
        float var = S2 * fmaf(a, fmaf(a, vw, 2.0f * cv), vb);
        float t = SCALE * rsqrtf(var + LN_EPS);
        float c0 = t * a;

        float4 o;
        o.x = fmaf(c0, P.x, fmaf(t, Q.x, be4.x));
        o.y = fmaf(c0, P.y, fmaf(t, Q.y, be4.y));
        o.z = fmaf(c0, P.z, fmaf(t, Q.z, be4.z));
        o.w = fmaf(c0, P.w, fmaf(t, Q.w, be4.w));

        __stcs(obase + (size_t)r * QUADS, o);  // streaming: never re-read
    }
}

extern "C" void kernel_launch(void* const* d_in, const int* in_sizes, int n_in,
                              void* d_out, int out_size) {
    const float* x  = (const float*)d_in[0];   // (2048, 32)
    const float* W  = (const float*)d_in[1];   // (1024, 1)
    const float* B  = (const float*)d_in[2];   // (1024,)
    const float* G  = (const float*)d_in[3];   // (1024,)
    const float* Be = (const float*)d_in[4];   // (1024,)
    float* out = (float*)d_out;

    int nrows = in_sizes[0];                   // 65536 rows

    int grid = NSM * CTAS_PER_SM;              // 1184: exactly one wave
    int maxg = (nrows + 1) / 2;                // keep >=2 rows/block for tiny inputs
    if (grid > maxg) grid = maxg > 0 ? maxg : 1;

    il_fused_kernel<<<grid, QUADS>>>(x, W, B, G, Be, out, nrows);
}

// round 6
// speedup vs baseline: 1.0007x; 1.0007x over previous
#include <cuda_runtime.h>
#include <math.h>

// InputLayer: out[b,n,d] = LN_d( (x[b,n]*W[d] + bias[d]) * sqrt(1024) ) * gamma[d] + beta[d]
// Analytic LayerNorm (h affine in a=x[b,n]) -> closed-form mean/var from W/b stats.
// Single kernel. Grid = 148 SMs * 6 CTAs = 888 (empirically best concurrency,
// exactly one wave), rows split evenly (73-74 per block).

#define SIZE 1024
#define QUADS (SIZE / 4)          // 256 threads per block
#define MAXR 96                   // max rows per block (smem bound)
#define LN_EPS 1e-5f
#define NSM 148
#define CTAS_PER_SM 6

__global__ __launch_bounds__(QUADS, CTAS_PER_SM)
void il_fused_kernel(const float* __restrict__ x,
                     const float* __restrict__ W,
                     const float* __restrict__ B,
                     const float* __restrict__ G,
                     const float* __restrict__ Be,
                     float* __restrict__ out,
                     int nrows) {
    const float SCALE = 32.0f;                 // sqrt(1024)
    const float S2 = SCALE * SCALE;

    int q = threadIdx.x;                       // 0..255
    int d0 = q * 4;

    // Even contiguous row partition.
    int nb  = gridDim.x;
    int per = nrows / nb;
    int rem = nrows - per * nb;
    int row0 = blockIdx.x * per + (blockIdx.x < rem ? blockIdx.x : rem);
    int cnt  = per + (blockIdx.x < rem ? 1 : 0);

    __shared__ float xa[MAXR];
    __shared__ float red[5][8];                // 5 stats x 8 warps

    for (int r = q; r < cnt; r += QUADS) xa[r] = x[row0 + r];

    float4 w4  = *(const float4*)(W  + d0);
    float4 b4  = *(const float4*)(B  + d0);
    float4 g4  = *(const float4*)(G  + d0);
    float4 be4 = *(const float4*)(Be + d0);

    // ---- per-block stats reduction over the 1024 (W,b) columns ----
    float s0 = w4.x + w4.y + w4.z + w4.w;
    float s1 = b4.x + b4.y + b4.z + b4.w;
    float s2 = w4.x*w4.x + w4.y*w4.y + w4.z*w4.z + w4.w*w4.w;
    float s3 = b4.x*b4.x + b4.y*b4.y + b4.z*b4.z + b4.w*b4.w;
    float s4 = w4.x*b4.x + w4.y*b4.y + w4.z*b4.z + w4.w*b4.w;

    int lane = q & 31, warp = q >> 5;
    #pragma unroll
    for (int o = 16; o > 0; o >>= 1) {
        s0 += __shfl_down_sync(0xffffffffu, s0, o);
        s1 += __shfl_down_sync(0xffffffffu, s1, o);
        s2 += __shfl_down_sync(0xffffffffu, s2, o);
        s3 += __shfl_down_sync(0xffffffffu, s3, o);
        s4 += __shfl_down_sync(0xffffffffu, s4, o);
    }
    if (lane == 0) {
        red[0][warp] = s0; red[1][warp] = s1; red[2][warp] = s2;
        red[3][warp] = s3; red[4][warp] = s4;
    }
    __syncthreads();

    float t0 = 0.f, t1 = 0.f, t2 = 0.f, t3 = 0.f, t4 = 0.f;
    #pragma unroll
    for (int i = 0; i < 8; i++) {
        t0 += red[0][i]; t1 += red[1][i]; t2 += red[2][i];
        t3 += red[3][i]; t4 += red[4][i];
    }
    const float inv = 1.0f / (float)SIZE;
    float mw = t0 * inv, mb = t1 * inv;
    float vw = fmaf(-mw, mw, t2 * inv);        // Var(W)
    float vb = fmaf(-mb, mb, t3 * inv);        // Var(B)
    float cv = fmaf(-mw, mb, t4 * inv);        // Cov(W,B)

    // P = (W - meanW) * gamma ;  Q = (B - meanB) * gamma
    float4 P, Q;
    P.x = (w4.x - mw) * g4.x;  Q.x = (b4.x - mb) * g4.x;
    P.y = (w4.y - mw) * g4.y;  Q.y = (b4.y - mb) * g4.y;
    P.z = (w4.z - mw) * g4.z;  Q.z = (b4.z - mb) * g4.z;
    P.w = (w4.w - mw) * g4.w;  Q.w = (b4.w - mb) * g4.w;

    float4* obase = (float4*)(out + (size_t)row0 * SIZE + d0);

    #pragma unroll 4
    for (int r = 0; r < cnt; r++) {
        float a = xa[r];
        float var = S2 * fmaf(a, fmaf(a, vw, 2.0f * cv), vb);
        float t = SCALE * rsqrtf(var + LN_EPS);
        float c0 = t * a;

        float4 o;
        o.x = fmaf(c0, P.x, fmaf(t, Q.x, be4.x));
        o.y = fmaf(c0, P.y, fmaf(t, Q.y, be4.y));
        o.z = fmaf(c0, P.z, fmaf(t, Q.z, be4.z));
        o.w = fmaf(c0, P.w, fmaf(t, Q.w, be4.w));

        __stcs(obase + (size_t)r * QUADS, o);  // streaming: never re-read
    }
}

extern "C" void kernel_launch(void* const* d_in, const int* in_sizes, int n_in,
                              void* d_out, int out_size) {
    const float* x  = (const float*)d_in[0];   // (2048, 32)
    const float* W  = (const float*)d_in[1];   // (1024, 1)
    const float* B  = (const float*)d_in[2];   // (1024,)
    const float* G  = (const float*)d_in[3];   // (1024,)
    const float* Be = (const float*)d_in[4];   // (1024,)
    float* out = (float*)d_out;

    int nrows = in_sizes[0];                   // 65536 rows

    int grid = NSM * CTAS_PER_SM;              // 888: exactly one wave @ 6 CTAs/SM
    // Cap so every block has work and rows/block <= MAXR.
    if (grid > nrows) grid = nrows;
    int ming = (nrows + MAXR - 1) / MAXR;
    if (grid < ming) grid = ming;

    il_fused_kernel<<<grid, QUADS>>>(x, W, B, G, Be, out, nrows);
}